// round 14
// baseline (speedup 1.0000x reference)
#include <cuda_runtime.h>
#include <cuda_bf16.h>

#define BLOCK 1024
#define GRID  304            // 152 SMs * 2 CTAs
#define MAX_MOL 4096
#define PACK_WORDS_CAP (1 << 20)     // u32 words; 16 atoms/word -> up to 16M atoms

__device__ unsigned g_packed[PACK_WORDS_CAP];

__device__ __forceinline__ float rcp_fast(float x) {
    float r; asm("rcp.approx.ftz.f32 %0, %1;" : "=f"(r) : "f"(x)); return r;
}
__device__ __forceinline__ float ex2_fast(float x) {
    float r; asm("ex2.approx.ftz.f32 %0, %1;" : "=f"(r) : "f"(x)); return r;
}

// ---------------------------------------------------------------------------
// Prep: ONE pass over species -> packed 2-bit table AND float conversion,
// plus energies init. Grid-stride, high thread count, MLP-4 loads.
// ---------------------------------------------------------------------------
__global__ void prep_kernel(const int* __restrict__ sp,
                            const float* __restrict__ energies,
                            float* __restrict__ out,
                            int n_species, int n_mol, int with_species) {
    const int stride  = gridDim.x * blockDim.x;
    const int tid0    = blockIdx.x * blockDim.x + threadIdx.x;
    const int n_words = (n_species + 15) >> 4;

    for (int i = tid0; i < n_words; i += stride) {
        int base = i * 16;
        unsigned v = 0;
        if (base + 16 <= n_species) {
            const int4* p = (const int4*)(sp + base);
            int4 s0 = p[0], s1 = p[1], s2 = p[2], s3 = p[3];
            v  = ((unsigned)s0.x & 3u)        | ((unsigned)s0.y & 3u) << 2
               | ((unsigned)s0.z & 3u) << 4   | ((unsigned)s0.w & 3u) << 6
               | ((unsigned)s1.x & 3u) << 8   | ((unsigned)s1.y & 3u) << 10
               | ((unsigned)s1.z & 3u) << 12  | ((unsigned)s1.w & 3u) << 14
               | ((unsigned)s2.x & 3u) << 16  | ((unsigned)s2.y & 3u) << 18
               | ((unsigned)s2.z & 3u) << 20  | ((unsigned)s2.w & 3u) << 22
               | ((unsigned)s3.x & 3u) << 24  | ((unsigned)s3.y & 3u) << 26
               | ((unsigned)s3.z & 3u) << 28  | ((unsigned)s3.w & 3u) << 30;
            if (with_species) {
                float4* o = (float4*)(out + base);
                o[0] = make_float4((float)s0.x, (float)s0.y, (float)s0.z, (float)s0.w);
                o[1] = make_float4((float)s1.x, (float)s1.y, (float)s1.z, (float)s1.w);
                o[2] = make_float4((float)s2.x, (float)s2.y, (float)s2.z, (float)s2.w);
                o[3] = make_float4((float)s3.x, (float)s3.y, (float)s3.z, (float)s3.w);
            }
        } else {
            for (int k = 0; base + k < n_species; k++) {
                int a = sp[base + k];
                v |= ((unsigned)a & 3u) << (2 * k);
                if (with_species) out[base + k] = (float)a;
            }
        }
        g_packed[i] = v;
    }

    float* oe = with_species ? (out + n_species) : out;
    for (int i = tid0; i < n_mol; i += stride)
        oe[i] = energies[i];
}

// ---------------------------------------------------------------------------
// Main kernel (R10-proven structure).
// Dynamic smem: [ hist MAX_MOL f32 ][ pre_rep 512 ][ df_rep 512 ][ tbl n_words ]
// pre_rep[t*32+lane] = ep[t]*e ; df_rep[t*32+lane] = df[t]*A2B*log2e
// srb = pre_e[t] * 2^( df2[t]*dd - log2e/(1-x2) ),  x2 = (dd/5.2)^2
// ---------------------------------------------------------------------------
template <bool POW2, bool SMEM_TBL>
__global__ __launch_bounds__(BLOCK, 2) void srb_kernel(
    const int*   __restrict__ idx12,
    const float* __restrict__ dist,
    const float* __restrict__ ep,
    const float* __restrict__ df,
    float*       __restrict__ out_energy,
    int n_pairs, int shift, int n_atoms, int n_mol, int n_words)
{
    extern __shared__ unsigned char smem_raw[];
    float*    hist    = (float*)smem_raw;
    float*    pre_rep = (float*)(smem_raw + MAX_MOL * sizeof(float));
    float*    df_rep  = pre_rep + 512;
    unsigned* tbl     = (unsigned*)(df_rep + 512);

    const float A2B    = 1.8897261258369282f;
    const float LOG2E  = 1.4426950408889634f;
    const float kEuler = 2.7182818284590452f;
    const float c1     = 1.0f / (5.2f * 5.2f);

    for (int i = threadIdx.x; i < MAX_MOL; i += BLOCK) hist[i] = 0.0f;
    if (threadIdx.x < 512) {
        int t = threadIdx.x >> 5;
        pre_rep[threadIdx.x] = ep[t] * kEuler;
        df_rep[threadIdx.x]  = df[t] * A2B * LOG2E;
    }
    if (SMEM_TBL) {
        for (int i = threadIdx.x; i < n_words; i += BLOCK)
            tbl[i] = g_packed[i];
    }
    __syncthreads();

    const unsigned lane = threadIdx.x & 31u;
    const int nvec = n_pairs >> 2;
    const int4*   iv1 = (const int4*)idx12;
    const int4*   iv2 = (const int4*)(idx12 + n_pairs);
    const float4* dv  = (const float4*)dist;

    const int stride = GRID * BLOCK;
    for (int p = blockIdx.x * BLOCK + threadIdx.x; p < nvec; p += stride) {
        int4   a = __ldcs(&iv1[p]);
        int4   b = __ldcs(&iv2[p]);
        float4 w = __ldcs(&dv[p]);

        int   i1[4] = {a.x, a.y, a.z, a.w};
        int   i2[4] = {b.x, b.y, b.z, b.w};
        float dd[4] = {w.x, w.y, w.z, w.w};

#pragma unroll
        for (int k = 0; k < 4; k++) {
            float x2 = dd[k] * dd[k] * c1;
            if (x2 < 1.0f) {
                unsigned u1 = (unsigned)i1[k];
                unsigned u2 = (unsigned)i2[k];
                unsigned w1 = SMEM_TBL ? tbl[u1 >> 4] : __ldg(&g_packed[u1 >> 4]);
                unsigned w2 = SMEM_TBL ? tbl[u2 >> 4] : __ldg(&g_packed[u2 >> 4]);
                unsigned sa = (w1 >> ((u1 & 15u) * 2u)) & 3u;
                unsigned sb = (w2 >> ((u2 & 15u) * 2u)) & 3u;
                unsigned ti = (sa << 7) | (sb << 5) | lane;
                float r   = rcp_fast(1.0f - x2);
                float E2  = fmaf(-LOG2E, r, df_rep[ti] * dd[k]);
                float srb = pre_rep[ti] * ex2_fast(E2);
                unsigned mol = POW2 ? (u1 >> shift) : (u1 / (unsigned)n_atoms);
                atomicAdd(&hist[mol], srb);
            }
        }
    }

    // scalar tail
    if (blockIdx.x == 0) {
        for (int p = nvec * 4 + threadIdx.x; p < n_pairs; p += BLOCK) {
            unsigned u1 = (unsigned)idx12[p];
            unsigned u2 = (unsigned)idx12[p + n_pairs];
            float ddk = dist[p];
            float x2  = ddk * ddk * c1;
            if (x2 < 1.0f) {
                unsigned w1 = SMEM_TBL ? tbl[u1 >> 4] : __ldg(&g_packed[u1 >> 4]);
                unsigned w2 = SMEM_TBL ? tbl[u2 >> 4] : __ldg(&g_packed[u2 >> 4]);
                unsigned sa = (w1 >> ((u1 & 15u) * 2u)) & 3u;
                unsigned sb = (w2 >> ((u2 & 15u) * 2u)) & 3u;
                unsigned ti = (sa << 7) | (sb << 5) | lane;
                float r   = rcp_fast(1.0f - x2);
                float E2  = fmaf(-LOG2E, r, df_rep[ti] * ddk);
                float srb = pre_rep[ti] * ex2_fast(E2);
                unsigned mol = POW2 ? (u1 >> shift) : (u1 / (unsigned)n_atoms);
                atomicAdd(&hist[mol], srb);
            }
        }
    }
    __syncthreads();

    for (int i = threadIdx.x; i < n_mol; i += BLOCK) {
        float v = hist[i];
        if (v != 0.0f) atomicAdd(&out_energy[i], v);
    }
}

// ---------------------------------------------------------------------------
extern "C" void kernel_launch(void* const* d_in, const int* in_sizes, int n_in,
                              void* d_out, int out_size) {
    const int*   species  = (const int*)  d_in[0];
    const float* energies = (const float*)d_in[1];
    const int*   idx12    = (const int*)  d_in[2];
    const float* dist     = (const float*)d_in[3];
    const float* ep       = (const float*)d_in[4];
    const float* df       = (const float*)d_in[5];

    int n_species = in_sizes[0];
    int n_mol     = in_sizes[1];
    int n_pairs   = in_sizes[3];
    int n_atoms   = n_species / n_mol;
    int n_words   = (n_species + 15) >> 4;

    int with_species = (out_size > n_mol) ? 1 : 0;
    float* out        = (float*)d_out;
    float* out_energy = with_species ? (out + n_species) : out;

    int shift = -1;
    if (n_atoms > 0 && (n_atoms & (n_atoms - 1)) == 0) {
        shift = 0;
        int v = n_atoms;
        while (v > 1) { v >>= 1; shift++; }
    }

    prep_kernel<<<160, 512>>>(species, energies, out,
                              n_species, n_mol, with_species);

    size_t dyn_base = (size_t)MAX_MOL * 4 + 1024 * 4;  // hist + replicated tables
    size_t dyn_tbl  = dyn_base + (size_t)n_words * 4;
    bool use_smem_tbl = (n_mol <= MAX_MOL) && (dyn_tbl <= 96 * 1024);

    if (use_smem_tbl) {
        if (shift >= 0) {
            cudaFuncSetAttribute(srb_kernel<true, true>,
                                 cudaFuncAttributeMaxDynamicSharedMemorySize,
                                 (int)dyn_tbl);
            srb_kernel<true, true><<<GRID, BLOCK, dyn_tbl>>>(
                idx12, dist, ep, df, out_energy, n_pairs, shift, n_atoms, n_mol, n_words);
        } else {
            cudaFuncSetAttribute(srb_kernel<false, true>,
                                 cudaFuncAttributeMaxDynamicSharedMemorySize,
                                 (int)dyn_tbl);
            srb_kernel<false, true><<<GRID, BLOCK, dyn_tbl>>>(
                idx12, dist, ep, df, out_energy, n_pairs, shift, n_atoms, n_mol, n_words);
        }
    } else {
        if (shift >= 0) {
            cudaFuncSetAttribute(srb_kernel<true, false>,
                                 cudaFuncAttributeMaxDynamicSharedMemorySize,
                                 (int)dyn_base);
            srb_kernel<true, false><<<GRID, BLOCK, dyn_base>>>(
                idx12, dist, ep, df, out_energy, n_pairs, shift, n_atoms, n_mol, n_words);
        } else {
            cudaFuncSetAttribute(srb_kernel<false, false>,
                                 cudaFuncAttributeMaxDynamicSharedMemorySize,
                                 (int)dyn_base);
            srb_kernel<false, false><<<GRID, BLOCK, dyn_base>>>(
                idx12, dist, ep, df, out_energy, n_pairs, shift, n_atoms, n_mol, n_words);
        }
    }
}

// round 16
// speedup vs baseline: 1.5862x; 1.5862x over previous
#include <cuda_runtime.h>
#include <cuda_bf16.h>

#define BLOCK 1024
#define GRID  304            // 152 SMs * 2 CTAs
#define MAX_MOL 4096
#define PACK_WORDS_CAP (1 << 20)     // u32 words; 16 atoms/word -> up to 16M atoms

__device__ unsigned g_packed[PACK_WORDS_CAP];

// ---------------------------------------------------------------------------
// Prep: ONE pass over species -> packed 2-bit table AND float conversion,
// plus energies init. Grid-stride.
// ---------------------------------------------------------------------------
__global__ void prep_kernel(const int* __restrict__ sp,
                            const float* __restrict__ energies,
                            float* __restrict__ out,
                            int n_species, int n_mol, int with_species) {
    const int stride  = gridDim.x * blockDim.x;
    const int tid0    = blockIdx.x * blockDim.x + threadIdx.x;
    const int n_words = (n_species + 15) >> 4;

    for (int i = tid0; i < n_words; i += stride) {
        int base = i * 16;
        unsigned v = 0;
        if (base + 16 <= n_species) {
            const int4* p = (const int4*)(sp + base);
            int4 s0 = p[0], s1 = p[1], s2 = p[2], s3 = p[3];
            v  = ((unsigned)s0.x & 3u)        | ((unsigned)s0.y & 3u) << 2
               | ((unsigned)s0.z & 3u) << 4   | ((unsigned)s0.w & 3u) << 6
               | ((unsigned)s1.x & 3u) << 8   | ((unsigned)s1.y & 3u) << 10
               | ((unsigned)s1.z & 3u) << 12  | ((unsigned)s1.w & 3u) << 14
               | ((unsigned)s2.x & 3u) << 16  | ((unsigned)s2.y & 3u) << 18
               | ((unsigned)s2.z & 3u) << 20  | ((unsigned)s2.w & 3u) << 22
               | ((unsigned)s3.x & 3u) << 24  | ((unsigned)s3.y & 3u) << 26
               | ((unsigned)s3.z & 3u) << 28  | ((unsigned)s3.w & 3u) << 30;
            if (with_species) {
                float4* o = (float4*)(out + base);
                o[0] = make_float4((float)s0.x, (float)s0.y, (float)s0.z, (float)s0.w);
                o[1] = make_float4((float)s1.x, (float)s1.y, (float)s1.z, (float)s1.w);
                o[2] = make_float4((float)s2.x, (float)s2.y, (float)s2.z, (float)s2.w);
                o[3] = make_float4((float)s3.x, (float)s3.y, (float)s3.z, (float)s3.w);
            }
        } else {
            for (int k = 0; base + k < n_species; k++) {
                int a = sp[base + k];
                v |= ((unsigned)a & 3u) << (2 * k);
                if (with_species) out[base + k] = (float)a;
            }
        }
        g_packed[i] = v;
    }

    float* oe = with_species ? (out + n_species) : out;
    for (int i = tid0; i < n_mol; i += stride)
        oe[i] = energies[i];
}

// ---------------------------------------------------------------------------
// Main kernel — EXACT R10 source (proven 48.1us schedule; do not reorder).
// Dynamic smem: [ hist: MAX_MOL f32 ][ pre_rep: 512 f32 ][ df_rep: 512 f32 ]
//               [ species tbl: n_words u32 ]
// pre_rep[t*32+lane] = ep[t] * e ; df_rep[t*32+lane] = df[t] * A2B * log2e
// srb = pre_e[t] * 2^( df2[t]*dd - log2e/(1-x2) ),  x2 = (dd/5.2)^2
// ---------------------------------------------------------------------------
template <bool POW2, bool SMEM_TBL>
__global__ __launch_bounds__(BLOCK, 2) void srb_kernel(
    const int*   __restrict__ idx12,
    const float* __restrict__ dist,
    const float* __restrict__ ep,
    const float* __restrict__ df,
    float*       __restrict__ out_energy,
    int n_pairs, int shift, int n_atoms, int n_mol, int n_words)
{
    extern __shared__ unsigned char smem_raw[];
    float*    hist    = (float*)smem_raw;
    float*    pre_rep = (float*)(smem_raw + MAX_MOL * sizeof(float));
    float*    df_rep  = pre_rep + 512;
    unsigned* tbl     = (unsigned*)(df_rep + 512);

    const float A2B    = 1.8897261258369282f;
    const float LOG2E  = 1.4426950408889634f;
    const float kEuler = 2.7182818284590452f;
    const float c1     = 1.0f / (5.2f * 5.2f);   // (dd/5.2)^2, angstrom

    for (int i = threadIdx.x; i < MAX_MOL; i += BLOCK) hist[i] = 0.0f;
    if (threadIdx.x < 512) {
        int t = threadIdx.x >> 5;
        pre_rep[threadIdx.x] = ep[t] * kEuler;
        df_rep[threadIdx.x]  = df[t] * A2B * LOG2E;
    }
    if (SMEM_TBL) {
        for (int i = threadIdx.x; i < n_words; i += BLOCK)
            tbl[i] = g_packed[i];
    }
    __syncthreads();

    const unsigned lane = threadIdx.x & 31u;

    const int nvec = n_pairs >> 2;
    const int4*   iv1 = (const int4*)idx12;
    const int4*   iv2 = (const int4*)(idx12 + n_pairs);
    const float4* dv  = (const float4*)dist;

    const int stride = GRID * BLOCK;
    for (int p = blockIdx.x * BLOCK + threadIdx.x; p < nvec; p += stride) {
        int4   a = __ldcs(&iv1[p]);
        int4   b = __ldcs(&iv2[p]);
        float4 w = __ldcs(&dv[p]);

        int   i1[4] = {a.x, a.y, a.z, a.w};
        int   i2[4] = {b.x, b.y, b.z, b.w};
        float dd[4] = {w.x, w.y, w.z, w.w};

#pragma unroll
        for (int k = 0; k < 4; k++) {
            float x2 = dd[k] * dd[k] * c1;
            if (x2 < 1.0f) {
                unsigned u1 = (unsigned)i1[k];
                unsigned u2 = (unsigned)i2[k];
                unsigned w1 = SMEM_TBL ? tbl[u1 >> 4] : __ldg(&g_packed[u1 >> 4]);
                unsigned w2 = SMEM_TBL ? tbl[u2 >> 4] : __ldg(&g_packed[u2 >> 4]);
                unsigned sa = (w1 >> ((u1 & 15u) * 2u)) & 3u;
                unsigned sb = (w2 >> ((u2 & 15u) * 2u)) & 3u;
                unsigned ti = ((sa * 4u + sb) << 5) | lane;
                float rcp2 = __fdividef(LOG2E, 1.0f - x2);
                float E2   = fmaf(df_rep[ti], dd[k], -rcp2);
                float srb  = pre_rep[ti] * exp2f(E2);
                unsigned mol = POW2 ? (u1 >> shift) : (u1 / (unsigned)n_atoms);
                atomicAdd(&hist[mol], srb);
            }
        }
    }

    // scalar tail
    if (blockIdx.x == 0) {
        for (int p = nvec * 4 + threadIdx.x; p < n_pairs; p += BLOCK) {
            unsigned u1 = (unsigned)idx12[p];
            unsigned u2 = (unsigned)idx12[p + n_pairs];
            float ddk = dist[p];
            float x2  = ddk * ddk * c1;
            if (x2 < 1.0f) {
                unsigned w1 = SMEM_TBL ? tbl[u1 >> 4] : __ldg(&g_packed[u1 >> 4]);
                unsigned w2 = SMEM_TBL ? tbl[u2 >> 4] : __ldg(&g_packed[u2 >> 4]);
                unsigned sa = (w1 >> ((u1 & 15u) * 2u)) & 3u;
                unsigned sb = (w2 >> ((u2 & 15u) * 2u)) & 3u;
                unsigned ti = ((sa * 4u + sb) << 5) | lane;
                float rcp2 = __fdividef(LOG2E, 1.0f - x2);
                float E2   = fmaf(df_rep[ti], ddk, -rcp2);
                float srb  = pre_rep[ti] * exp2f(E2);
                unsigned mol = POW2 ? (u1 >> shift) : (u1 / (unsigned)n_atoms);
                atomicAdd(&hist[mol], srb);
            }
        }
    }
    __syncthreads();

    for (int i = threadIdx.x; i < n_mol; i += BLOCK) {
        float v = hist[i];
        if (v != 0.0f) atomicAdd(&out_energy[i], v);
    }
}

// ---------------------------------------------------------------------------
extern "C" void kernel_launch(void* const* d_in, const int* in_sizes, int n_in,
                              void* d_out, int out_size) {
    const int*   species  = (const int*)  d_in[0];
    const float* energies = (const float*)d_in[1];
    const int*   idx12    = (const int*)  d_in[2];
    const float* dist     = (const float*)d_in[3];
    const float* ep       = (const float*)d_in[4];
    const float* df       = (const float*)d_in[5];

    int n_species = in_sizes[0];
    int n_mol     = in_sizes[1];
    int n_pairs   = in_sizes[3];
    int n_atoms   = n_species / n_mol;
    int n_words   = (n_species + 15) >> 4;

    int with_species = (out_size > n_mol) ? 1 : 0;
    float* out        = (float*)d_out;
    float* out_energy = with_species ? (out + n_species) : out;

    int shift = -1;
    if (n_atoms > 0 && (n_atoms & (n_atoms - 1)) == 0) {
        shift = 0;
        int v = n_atoms;
        while (v > 1) { v >>= 1; shift++; }
    }

    prep_kernel<<<160, 512>>>(species, energies, out,
                              n_species, n_mol, with_species);

    size_t dyn_base = (size_t)MAX_MOL * 4 + 1024 * 4;  // hist + replicated tables
    size_t dyn_tbl  = dyn_base + (size_t)n_words * 4;
    bool use_smem_tbl = (n_mol <= MAX_MOL) && (dyn_tbl <= 96 * 1024);

    if (use_smem_tbl) {
        if (shift >= 0) {
            cudaFuncSetAttribute(srb_kernel<true, true>,
                                 cudaFuncAttributeMaxDynamicSharedMemorySize,
                                 (int)dyn_tbl);
            srb_kernel<true, true><<<GRID, BLOCK, dyn_tbl>>>(
                idx12, dist, ep, df, out_energy, n_pairs, shift, n_atoms, n_mol, n_words);
        } else {
            cudaFuncSetAttribute(srb_kernel<false, true>,
                                 cudaFuncAttributeMaxDynamicSharedMemorySize,
                                 (int)dyn_tbl);
            srb_kernel<false, true><<<GRID, BLOCK, dyn_tbl>>>(
                idx12, dist, ep, df, out_energy, n_pairs, shift, n_atoms, n_mol, n_words);
        }
    } else {
        if (shift >= 0) {
            cudaFuncSetAttribute(srb_kernel<true, false>,
                                 cudaFuncAttributeMaxDynamicSharedMemorySize,
                                 (int)dyn_base);
            srb_kernel<true, false><<<GRID, BLOCK, dyn_base>>>(
                idx12, dist, ep, df, out_energy, n_pairs, shift, n_atoms, n_mol, n_words);
        } else {
            cudaFuncSetAttribute(srb_kernel<false, false>,
                                 cudaFuncAttributeMaxDynamicSharedMemorySize,
                                 (int)dyn_base);
            srb_kernel<false, false><<<GRID, BLOCK, dyn_base>>>(
                idx12, dist, ep, df, out_energy, n_pairs, shift, n_atoms, n_mol, n_words);
        }
    }
}